// round 15
// baseline (speedup 1.0000x reference)
#include <cuda_runtime.h>

#define BB 32
#define NN 1024
#define FF 7
#define HID 256
#define MLPH 64
#define OUTD 8
#define THR2 0.09f
#define KCH 128         // K-chunks for MLP layer0
#define K4  14          // float4s per chunk (56 floats); 128*56 = 7168
#define SEGS 16         // kB segments per batch (64 rows each)
#define CAT (MLPH + HID + OUTD)   // 328
#define PBLK 512        // pair blocks: 16 per batch (4 row-groups x 4 j-groups)
#define NCAP 64         // neighbor-list capacity per (row, j-group)

// ---- device scratch ----
__device__ unsigned short g_nbr[(size_t)BB * 4 * NCAP * NN]; // slot-major, row-minor
__device__ int      g_cnt[BB * 4 * NN];         // neighbors per (b, jg, row)
__device__ float4   g_pack[BB * NN];            // (x, y, -, speed) per node
__device__ float    g_maxp[BB * 16];            // per-pair-block max dist^2 partials
__device__ float    g_upart[BB * SEGS * HID];   // per-seg partials of sum_j s_j h_j
__device__ float    g_speedp[BB * SEGS];        // per-seg speed sums
__device__ float    g_mpart[KCH * BB * MLPH];   // MLP layer0 K-chunk partials

// sbuf must cover MLP path: 14*64*4 + 14*32*4 floats = 21.5KB
#define SBUF_F (K4 * MLPH * 4 + K4 * BB * 4 + 16)

// ---- packed f32x2 helpers (sm_103a) ----
__device__ __forceinline__ unsigned long long pk2(float a, float b) {
    unsigned long long r;
    asm("mov.b64 %0, {%1, %2};" : "=l"(r) : "f"(a), "f"(b));
    return r;
}
__device__ __forceinline__ unsigned long long fma2(unsigned long long a,
                                                   unsigned long long b,
                                                   unsigned long long c) {
    unsigned long long r;
    asm("fma.rn.f32x2 %0, %1, %2, %3;" : "=l"(r) : "l"(a), "l"(b), "l"(c));
    return r;
}
__device__ __forceinline__ void up2(unsigned long long p, float& lo, float& hi) {
    asm("mov.b64 {%0, %1}, %2;" : "=f"(lo), "=f"(hi) : "l"(p));
}

// ============================================================================
// kA: blocks [0,512): pairwise adjacency -> neighbor lists (packed f32x2 math).
//     blocks [512,640): MLP0 chunk GEMM.
// ============================================================================
__global__ __launch_bounds__(256, 5) void kA(const float* __restrict__ x,
                                             const float* __restrict__ Wm0) {
    __shared__ float sbuf[SBUF_F];
    int t = threadIdx.x;

    if (blockIdx.x < PBLK) {
        // layout: s_xy ull2[128] (4KB... 2KB) | s_r ull[128] (1KB) | s_max[8]
        ulonglong2*         s_xy = (ulonglong2*)sbuf;             // (xpair, ypair)
        unsigned long long* s_r  = (unsigned long long*)(sbuf + 512);
        float*              s_max = sbuf + 768;
        int b   = blockIdx.x >> 4;
        int sub = blockIdx.x & 15;
        int rg = sub >> 2, jg = sub & 3;
        int row0 = rg << 8, j0 = jg << 8;
        int lane = t & 31, w = t >> 5;

        if (t < 128) {   // stage 2 j-points per thread, pre-packed
            const float* xr0 = x + ((size_t)b * NN + j0 + 2 * t) * FF;
            float x0 = xr0[1], y0 = xr0[2];
            float x1 = xr0[FF + 1], y1 = xr0[FF + 2];
            float r0 = fmaf(x0, x0, y0 * y0);
            float r1 = fmaf(x1, x1, y1 * y1);
            s_xy[t] = make_ulonglong2(pk2(x0, x1), pk2(y0, y1));
            s_r[t]  = pk2(r0, r1);
        }
        __syncthreads();

        int row = row0 + t;
        const float* xrow = x + ((size_t)b * NN + row) * FF;
        float xi = xrow[1], yi = xrow[2];
        float ri = fmaf(xi, xi, yi * yi);
        float thri = THR2 - ri;
        unsigned long long nx2 = pk2(-2.f * xi, -2.f * xi);
        unsigned long long ny2 = pk2(-2.f * yi, -2.f * yi);
        float smaxlo = -3.4e38f, smaxhi = -3.4e38f;
        unsigned words[8];

#pragma unroll
        for (int wd = 0; wd < 8; ++wd) {
            unsigned word = 0;
#pragma unroll
            for (int k = 0; k < 16; ++k) {
                ulonglong2 xy = s_xy[wd * 16 + k];
                unsigned long long s2 = fma2(ny2, xy.y, fma2(nx2, xy.x, s_r[wd * 16 + k]));
                float slo, shi; up2(s2, slo, shi);
                smaxlo = fmaxf(smaxlo, slo);
                smaxhi = fmaxf(smaxhi, shi);
                if (slo < thri) word |= (1u << (2 * k));
                if (shi < thri) word |= (1u << (2 * k + 1));
            }
            words[wd] = word;
        }

        // slot-synchronized neighbor-list emission (coalesced u16 stores)
        {
            const size_t nbase = ((size_t)(b * 4 + jg) * NCAP) * NN + row;
            int wd = 0; unsigned cur = words[0]; int cnt = 0;
            for (int slot = 0; slot < NCAP; ++slot) {
                while (cur == 0 && wd < 7) cur = words[++wd];
                unsigned act = __ballot_sync(0xffffffffu, cur != 0);
                if (!act) break;
                if (cur) {
                    int j = j0 + (wd << 5) + __ffs(cur) - 1;
                    cur &= cur - 1;
                    g_nbr[nbase + (size_t)slot * NN] = (unsigned short)j;
                    ++cnt;
                }
            }
            g_cnt[(b * 4 + jg) * NN + row] = cnt;
        }

        if (jg == 0) {
            float s3 = xrow[3], s4 = xrow[4];
            g_pack[b * NN + row] = make_float4(
                xi, yi, 0.f, sqrtf(fmaf(s3, s3, s4 * s4)));
        }

        float mx = fmaxf(smaxlo, smaxhi) + ri;
        for (int o = 16; o > 0; o >>= 1)
            mx = fmaxf(mx, __shfl_xor_sync(0xffffffffu, mx, o));
        if (lane == 0) s_max[w] = mx;
        __syncthreads();
        if (t == 0) {
            float m = s_max[0];
#pragma unroll
            for (int k = 1; k < 8; ++k) m = fmaxf(m, s_max[k]);
            g_maxp[b * 16 + sub] = m;
        }
    } else {
        int c = blockIdx.x - PBLK;
        float4* sw4 = (float4*)sbuf;                       // [K4][64]
        float4* sx4 = (float4*)(sbuf + K4 * MLPH * 4);     // [K4][32]
        const float4* W4 = (const float4*)Wm0;
        const float4* X4 = (const float4*)x;

        for (int i = t; i < MLPH * K4; i += 256) {
            int h = i / K4, k = i % K4;
            sw4[k * MLPH + h] = W4[(size_t)h * 1792 + c * K4 + k];
        }
        for (int i = t; i < BB * K4; i += 256) {
            int b = i / K4, k = i % K4;
            sx4[k * BB + b] = X4[(size_t)b * 1792 + c * K4 + k];
        }
        __syncthreads();

        int hb = t & 15;
        int bbase = t >> 4;
        float acc[2][4] = {};
#pragma unroll
        for (int k = 0; k < K4; ++k) {
            float4 xv[2];
#pragma unroll
            for (int i = 0; i < 2; ++i) xv[i] = sx4[k * BB + bbase + 16 * i];
#pragma unroll
            for (int j = 0; j < 4; ++j) {
                float4 wv = sw4[k * MLPH + hb + 16 * j];
#pragma unroll
                for (int i = 0; i < 2; ++i) {
                    acc[i][j] = fmaf(xv[i].x, wv.x, acc[i][j]);
                    acc[i][j] = fmaf(xv[i].y, wv.y, acc[i][j]);
                    acc[i][j] = fmaf(xv[i].z, wv.z, acc[i][j]);
                    acc[i][j] = fmaf(xv[i].w, wv.w, acc[i][j]);
                }
            }
        }
#pragma unroll
        for (int i = 0; i < 2; ++i)
#pragma unroll
            for (int j = 0; j < 4; ++j)
                g_mpart[((size_t)c * BB + bbase + 16 * i) * MLPH + hb + 16 * j] = acc[i][j];
    }
}

// ============================================================================
// kB: sparse graph pass, thread-per-row list scan. Block = (batch, 64-row seg).
// ============================================================================
__global__ __launch_bounds__(256) void kB(const float* __restrict__ W1,
                                          const float* __restrict__ b1) {
    __shared__ float4 s_pack[NN];    // 16KB (x, y, dinv, speed)
    __shared__ float4 s_P[64];
    __shared__ float  sred[64];
    int b = blockIdx.x >> 4, seg = blockIdx.x & 15;
    int row0 = seg * 64;
    int t = threadIdx.x;

    const float4* packb = g_pack + (size_t)b * NN;
    const int* cntb = g_cnt + b * 4 * NN;
    for (int j = t; j < NN; j += 256) {
        float4 p = packb[j];
        int d = cntb[j] + cntb[NN + j] + cntb[2 * NN + j] + cntb[3 * NN + j];
        p.z = rsqrtf((float)d);
        s_pack[j] = p;
    }
    __syncthreads();

    if (t < 64) {
        int row = row0 + t;
        float wsum = 0.f, px = 0.f, py = 0.f;
#pragma unroll
        for (int jg = 0; jg < 4; ++jg) {
            int c = cntb[jg * NN + row];
            const unsigned short* nb = g_nbr + ((size_t)(b * 4 + jg) * NCAP) * NN + row;
            for (int k = 0; k < c; ++k) {
                int j = nb[(size_t)k * NN];
                float4 p = s_pack[j];
                wsum += p.z;
                px = fmaf(p.z, p.x, px);
                py = fmaf(p.z, p.y, py);
            }
        }
        float di = s_pack[row].z;
        s_P[t] = make_float4(di * px, di * py, di * wsum, 0.f);
        sred[t] = s_pack[row].w;
    }
    __syncthreads();

    for (int o = 32; o > 0; o >>= 1) {
        if (t < o) sred[t] += sred[t + o];
        __syncthreads();
    }
    if (t == 0) g_speedp[b * SEGS + seg] = sred[0];

    float w10 = W1[2 * t], w11 = W1[2 * t + 1], bk = b1[t];
    float acc = 0.f;
#pragma unroll 8
    for (int r = 0; r < 64; ++r) {
        float4 P = s_P[r];
        float h = fmaxf(fmaf(w10, P.x, fmaf(w11, P.y, bk)), 0.f);
        acc = fmaf(P.z, h, acc);
    }
    g_upart[((size_t)b * SEGS + seg) * HID + t] = acc;
}

// ============================================================================
// k3: per-batch finals — all matvecs warp-per-row, coalesced, shuffle reduce.
// ============================================================================
__global__ __launch_bounds__(256) void k3_final(
                         const float* __restrict__ W2,  const float* __restrict__ b2,
                         const float* __restrict__ Wfc, const float* __restrict__ bfc,
                         const float* __restrict__ Wg,  const float* __restrict__ bg,
                         const float* __restrict__ Wm1, const float* __restrict__ bm1,
                         const float* __restrict__ bm0,
                         const float* __restrict__ Wp,  const float* __restrict__ bp,
                         float* __restrict__ out) {
    __shared__ __align__(16) float sm[HID];
    __shared__ __align__(16) float smid[HID];
    __shared__ float sy0p[4][MLPH];
    __shared__ __align__(16) float sy0[MLPH];
    __shared__ __align__(16) float svec[CAT];   // [sy1(64) | sgcn(256) | sglo(8)]
    int b = blockIdx.x, t = threadIdx.x, lane = t & 31, w = t >> 5;

    float u = 0.f;
#pragma unroll
    for (int c = 0; c < SEGS; ++c) u += g_upart[((size_t)b * SEGS + c) * HID + t];
    sm[t] = u * (1.0f / 1024.0f);

    {
        int h = t & 63, grp = t >> 6;
        float a = 0.f;
#pragma unroll 8
        for (int k = 0; k < KCH / 4; ++k)
            a += g_mpart[((size_t)(grp * (KCH / 4) + k) * BB + b) * MLPH + h];
        sy0p[grp][h] = a;
    }
    __syncthreads();
    if (t < MLPH)
        sy0[t] = fmaxf(sy0p[0][t] + sy0p[1][t] + sy0p[2][t] + sy0p[3][t] + bm0[t], 0.f);
    __syncthreads();

#pragma unroll
    for (int k = 0; k < 8; ++k) {
        int r = w * 8 + k;
        float v = fmaf(Wm1[r * MLPH + lane], sy0[lane],
                       Wm1[r * MLPH + 32 + lane] * sy0[32 + lane]);
#pragma unroll
        for (int o = 16; o > 0; o >>= 1) v += __shfl_xor_sync(0xffffffffu, v, o);
        if (lane == 0) svec[r] = fmaxf(v + bm1[r], 0.f);
    }

    const float4* sm4 = (const float4*)sm;
    float4 m0 = sm4[lane], m1 = sm4[lane + 32];
#pragma unroll 4
    for (int k = 0; k < 32; ++k) {
        int r = w * 32 + k;
        const float4* wr = (const float4*)(W2 + (size_t)r * HID);
        float4 w0 = wr[lane], w1 = wr[lane + 32];
        float v = w0.x * m0.x + w0.y * m0.y + w0.z * m0.z + w0.w * m0.w
                + w1.x * m1.x + w1.y * m1.y + w1.z * m1.z + w1.w * m1.w;
#pragma unroll
        for (int o = 16; o > 0; o >>= 1) v += __shfl_xor_sync(0xffffffffu, v, o);
        if (lane == 0) smid[r] = v + b2[r];
    }
    __syncthreads();

    const float4* sd4 = (const float4*)smid;
    float4 d0 = sd4[lane], d1 = sd4[lane + 32];
#pragma unroll 4
    for (int k = 0; k < 32; ++k) {
        int r = w * 32 + k;
        const float4* wr = (const float4*)(Wfc + (size_t)r * HID);
        float4 w0 = wr[lane], w1 = wr[lane + 32];
        float v = w0.x * d0.x + w0.y * d0.y + w0.z * d0.z + w0.w * d0.w
                + w1.x * d1.x + w1.y * d1.y + w1.z * d1.z + w1.w * d1.w;
#pragma unroll
        for (int o = 16; o > 0; o >>= 1) v += __shfl_xor_sync(0xffffffffu, v, o);
        if (lane == 0) svec[MLPH + r] = v + bfc[r];
    }

    if (t < OUTD) {
        float avg = 0.f;
#pragma unroll
        for (int c = 0; c < SEGS; ++c) avg += g_speedp[b * SEGS + c];
        avg *= (1.0f / 1024.0f);
        float mx = g_maxp[b * 16];
#pragma unroll
        for (int k = 1; k < 16; ++k) mx = fmaxf(mx, g_maxp[b * 16 + k]);
        float den = rsqrtf(mx);
        svec[MLPH + HID + t] =
            fmaxf(fmaf(Wg[t * 2], avg, fmaf(Wg[t * 2 + 1], den, bg[t])), 0.f);
    }
    __syncthreads();

    if (w < OUTD) {
        const float* wp = Wp + (size_t)w * CAT;
        float o = 0.f;
#pragma unroll
        for (int j = lane; j < CAT; j += 32) o = fmaf(wp[j], svec[j], o);
#pragma unroll
        for (int s = 16; s > 0; s >>= 1) o += __shfl_xor_sync(0xffffffffu, o, s);
        if (lane == 0) out[b * OUTD + w] = o + bp[w];
    }
}

extern "C" void kernel_launch(void* const* d_in, const int* in_sizes, int n_in,
                              void* d_out, int out_size) {
    const float* x   = (const float*)d_in[0];
    const float* W1  = (const float*)d_in[1];
    const float* b1  = (const float*)d_in[2];
    const float* W2  = (const float*)d_in[3];
    const float* b2  = (const float*)d_in[4];
    const float* Wfc = (const float*)d_in[5];
    const float* bfc = (const float*)d_in[6];
    const float* Wg  = (const float*)d_in[7];
    const float* bg  = (const float*)d_in[8];
    const float* Wm0 = (const float*)d_in[9];
    const float* bm0 = (const float*)d_in[10];
    const float* Wm1 = (const float*)d_in[11];
    const float* bm1 = (const float*)d_in[12];
    const float* Wp  = (const float*)d_in[13];
    const float* bp  = (const float*)d_in[14];
    float* out = (float*)d_out;

    kA<<<PBLK + KCH, 256>>>(x, Wm0);
    kB<<<512, 256>>>(W1, b1);
    k3_final<<<32, 256>>>(W2, b2, Wfc, bfc, Wg, bg, Wm1, bm1, bm0, Wp, bp, out);
}